// round 17
// baseline (speedup 1.0000x reference)
#include <cuda_runtime.h>
#include <cuda_fp16.h>
#include <math.h>
#include <stdint.h>

#define BB   8
#define NN   8192
#define SS   2048
#define C1c  128
#define C2c  256
#define CIN  384
#define TT   256
#define CO   256
#define COUNT_BN (BB*NN)

// ---------------- scratch (device globals) ----------------
__device__ float  d_p2t[BB*SS*C2c];                 // points2 transposed (B,S,C2)
__device__ int    d_idx3[BB*NN*3];
__device__ float  d_w3[BB*NN*3];
__device__ __half d_itph[(size_t)BB*C2c*NN];        // interpolated channels, fp16
__device__ __half d_y1h[(size_t)BB*CO*NN];          // layer1 output, fp16
__device__ __half d_y2h[(size_t)BB*CO*NN];          // layer2 raw output, fp16
__device__ float  d_bias1[BB*CO];
__device__ float  d_bias2[BB*CO];
__device__ float  d_sum1[CO], d_sq1[CO], d_sum2[CO], d_sq2[CO];
// fp16 A images in m16n8k16 fragment order
__device__ __half d_w1img[CO*CIN];
__device__ __half d_w2img[CO*CO];

// mega-kernel block ranges
#define MB_TOP3   1024                   // (NN/64)*BB = 128*8: 64 pts x 4 scan-quadrants
#define MB_TRANS  4096                   // 64*8*BB
#define MB_PERM1  384                    // CO*CIN/256
#define MB_PERM2  256                    // CO*CO/256
#define MB_BIAS   BB
#define MB_TOTAL  (MB_TOP3 + MB_TRANS + MB_PERM1 + MB_PERM2 + MB_BIAS)

__device__ __forceinline__ float gelu_exact(float x) {
    return 0.5f * x * (1.0f + erff(x * 0.7071067811865476f));
}
__device__ __forceinline__ uint32_t smem_u32(const void* p) {
    uint32_t a;
    asm("{ .reg .u64 tmp; cvta.to.shared.u64 tmp, %1; cvt.u32.u64 %0, tmp; }" : "=r"(a) : "l"(p));
    return a;
}
__device__ __forceinline__ void cp16(uint32_t dst, const void* src) {
    asm volatile("cp.async.cg.shared.global [%0], [%1], 16;" :: "r"(dst), "l"(src));
}
__device__ __forceinline__ void cp_commit() { asm volatile("cp.async.commit_group;" ::: "memory"); }
__device__ __forceinline__ void cp_wait0()  { asm volatile("cp.async.wait_group 0;" ::: "memory"); }

#define MMA_F16(d, a, b0, b1)                                                     \
    asm volatile("mma.sync.aligned.m16n8k16.row.col.f32.f16.f16.f32 "             \
                 "{%0,%1,%2,%3}, {%4,%5,%6,%7}, {%8,%9}, {%0,%1,%2,%3};"          \
                 : "+f"(d[0]), "+f"(d[1]), "+f"(d[2]), "+f"(d[3])                 \
                 : "r"(a.x), "r"(a.y), "r"(a.z), "r"(a.w), "r"(b0), "r"(b1))

// ---------------- weight permute body (fp16 m16n8k16 fragment order) ----------------
__device__ __forceinline__ void permA16_body(const float* __restrict__ w,
                                             __half* __restrict__ img, int K, int idx)
{
    int o = idx / K, k = idx % K;
    int bm = o >> 4, r = o & 15;
    int g = r & 7, hi = r >> 3;
    int kt = k >> 5, kl = k & 31;
    int bk = kl >> 4, kk = kl & 15;
    int tq  = (kk & 7) >> 1;
    int khi = kk >> 3;
    int klo = kk & 1;
    int lane = g*4 + tq;
    int reg  = hi + 2*khi;
    size_t uidx = ((size_t)(kt*16 + bm)*2 + bk)*128 + lane*4 + reg;
    img[uidx*2 + klo] = __float2half_rn(w[idx]);
}

// ---------------- mega: top3(4-way split) + transpose + perms + biases + stat zero ----------------
__global__ void __launch_bounds__(256) mega_prep(
    const float* __restrict__ xyz1, const float* __restrict__ xyz2,
    const float* __restrict__ points2, const float* __restrict__ t_embed,
    const float* __restrict__ w_t1, const float* __restrict__ b_t1,
    const float* __restrict__ w_c1, const float* __restrict__ b_c1,
    const float* __restrict__ w_t2, const float* __restrict__ b_t2,
    const float* __restrict__ w_c2, const float* __restrict__ b_c2)
{
    __shared__ __align__(16) char smem_raw[32768];
    int blk = blockIdx.x, t = threadIdx.x;

    if (blk < MB_TOP3) {
        // ---- 3-NN top3: 64 points x 4 scan-quadrants (512 candidates each) ----
        float4* sq = (float4*)smem_raw;           // SS entries = 32KB
        int b    = blk >> 7;                       // 128 blocks per batch
        int nblk = blk & 127;                      // 64-point group
        const float* x2 = xyz2 + (size_t)b*SS*3;
        for (int i = t; i < SS; i += 256) {
            float a = x2[i*3+0], bb = x2[i*3+1], c = x2[i*3+2];
            float4 q;
            q.x = -2.0f*a; q.y = -2.0f*bb; q.z = -2.0f*c;
            q.w = a*a + bb*bb + c*c;
            sq[i] = q;
        }
        __syncthreads();
        int qd = t >> 6, p = t & 63;
        int n = nblk*64 + p;
        const float* pt = xyz1 + ((size_t)b*NN + n)*3;
        float px = pt[0], py = pt[1], pz = pt[2];
        float e0 = 3.4e38f, e1 = 3.4e38f, e2 = 3.4e38f;
        int   i0 = 0, i1 = 0, i2 = 0;
        int s0 = qd * (SS/4);
        #pragma unroll 4
        for (int s = s0; s < s0 + SS/4; s++) {
            float4 q = sq[s];
            float e = fmaf(px, q.x, fmaf(py, q.y, fmaf(pz, q.z, q.w)));
            if (e < e2) {
                e2 = e; i2 = s;
                if (e2 < e1) {
                    float te = e1; e1 = e2; e2 = te;
                    int   ti = i1; i1 = i2; i2 = ti;
                    if (e1 < e0) {
                        te = e0; e0 = e1; e1 = te;
                        ti = i0; i0 = i1; i1 = ti;
                    }
                }
            }
        }
        __syncthreads();                           // done with sq; reuse smem
        float* me = (float*)smem_raw;              // [256][3]
        int*   mi = (int*)(smem_raw + 256*3*4);    // [256][3]
        me[t*3+0] = e0; me[t*3+1] = e1; me[t*3+2] = e2;
        mi[t*3+0] = i0; mi[t*3+1] = i1; mi[t*3+2] = i2;
        __syncthreads();
        if (qd == 0) {
            float E0 = 3.4e38f, E1 = 3.4e38f, E2 = 3.4e38f;
            int   I0 = 0, I1 = 0, I2 = 0;
            #pragma unroll
            for (int qq = 0; qq < 4; qq++) {
                int base = (qq*64 + p)*3;
                #pragma unroll
                for (int r = 0; r < 3; r++) {
                    float e = me[base + r];
                    int   ii = mi[base + r];
                    if (e < E2) {
                        E2 = e; I2 = ii;
                        if (E2 < E1) {
                            float te = E1; E1 = E2; E2 = te;
                            int   ti = I1; I1 = I2; I2 = ti;
                            if (E1 < E0) {
                                te = E0; E0 = E1; E1 = te;
                                ti = I0; I0 = I1; I1 = ti;
                            }
                        }
                    }
                }
            }
            float n1 = px*px + py*py + pz*pz;
            float d0 = n1 + E0, d1 = n1 + E1, d2 = n1 + E2;
            float r0 = 1.f/(d0 + 1e-8f), r1 = 1.f/(d1 + 1e-8f), r2 = 1.f/(d2 + 1e-8f);
            float inv = 1.f/(r0 + r1 + r2);
            size_t base = ((size_t)b*NN + n)*3;
            d_idx3[base+0] = I0; d_idx3[base+1] = I1; d_idx3[base+2] = I2;
            d_w3[base+0] = r0*inv; d_w3[base+1] = r1*inv; d_w3[base+2] = r2*inv;
        }
    } else if (blk < MB_TOP3 + MB_TRANS) {
        // ---- points2 transpose (B,C2,S) -> (B,S,C2) ----
        typedef float Tile[33];
        Tile* tile = (Tile*)smem_raw;
        int tb = blk - MB_TOP3;
        int b  = tb >> 9;
        int r  = tb & 511;
        int s0 = (r & 63) * 32;
        int c0 = (r >> 6) * 32;
        int tx = t & 31, ty = t >> 5;   // 32 x 8
        const float* src = points2 + (size_t)b*C2c*SS;
        float*       dst = d_p2t   + (size_t)b*SS*C2c;
        #pragma unroll
        for (int j = 0; j < 32; j += 8)
            tile[ty+j][tx] = src[(size_t)(c0+ty+j)*SS + s0 + tx];
        __syncthreads();
        #pragma unroll
        for (int j = 0; j < 32; j += 8)
            dst[(size_t)(s0+ty+j)*C2c + c0 + tx] = tile[tx][ty+j];
    } else if (blk < MB_TOP3 + MB_TRANS + MB_PERM1) {
        int idx = (blk - MB_TOP3 - MB_TRANS)*256 + t;
        permA16_body(w_c1, d_w1img, CIN, idx);
    } else if (blk < MB_TOP3 + MB_TRANS + MB_PERM1 + MB_PERM2) {
        int idx = (blk - MB_TOP3 - MB_TRANS - MB_PERM1)*256 + t;
        permA16_body(w_c2, d_w2img, CO, idx);
    } else {
        // ---- t-cond bias folding (256 threads) + stat zero ----
        float* g   = (float*)smem_raw;          // 256
        float* te1 = g + TT;                    // 384
        float* te2 = te1 + CIN;                 // 256
        int b = blk - (MB_TOP3 + MB_TRANS + MB_PERM1 + MB_PERM2);
        g[t] = gelu_exact(t_embed[b*TT + t]);
        __syncthreads();
        for (int c = t; c < CIN; c += 256) {
            float s = b_t1[c];
            const float* w = w_t1 + (size_t)c*TT;
            #pragma unroll 8
            for (int k = 0; k < TT; k++) s = fmaf(g[k], w[k], s);
            te1[c] = s;
        }
        {
            float s = b_t2[t];
            const float* w = w_t2 + (size_t)t*TT;
            #pragma unroll 8
            for (int k = 0; k < TT; k++) s = fmaf(g[k], w[k], s);
            te2[t] = s;
        }
        __syncthreads();
        {
            float s1 = b_c1[t];
            const float* w1 = w_c1 + (size_t)t*CIN;
            #pragma unroll 8
            for (int k = 0; k < CIN; k++) s1 = fmaf(te1[k], w1[k], s1);
            d_bias1[b*CO + t] = s1;
            float s2 = b_c2[t];
            const float* w2 = w_c2 + (size_t)t*CO;
            #pragma unroll 8
            for (int k = 0; k < CO; k++) s2 = fmaf(te2[k], w2[k], s2);
            d_bias2[b*CO + t] = s2;
        }
        if (b == 0) {
            d_sum1[t] = 0.f; d_sq1[t] = 0.f; d_sum2[t] = 0.f; d_sq2[t] = 0.f;
        }
    }
}

// ---------------- 3-NN interpolation into d_itph, float4 gather ----------------
__global__ void __launch_bounds__(256) interp_kernel()
{
    __shared__ __half sc[C2c][34];
    __shared__ int    sidx[32*3];
    __shared__ float  swt[32*3];
    int b  = blockIdx.y;
    int n0 = blockIdx.x * 32;
    int t  = threadIdx.x;
    if (t < 96) {
        size_t base = ((size_t)b*NN + n0)*3;
        sidx[t] = d_idx3[base + t];
        swt[t]  = d_w3[base + t];
    }
    __syncthreads();
    const float* p2t = d_p2t + (size_t)b*SS*C2c;
    int q  = t & 63;          // channel quad
    int pg = t >> 6;          // point group (0..3)
    int c0 = q * 4;
    #pragma unroll
    for (int p = 0; p < 8; p++) {
        int nl = pg + p*4;    // point 0..31
        int   j0 = sidx[nl*3+0], j1 = sidx[nl*3+1], j2 = sidx[nl*3+2];
        float w0 = swt[nl*3+0],  w1 = swt[nl*3+1],  w2 = swt[nl*3+2];
        float4 v0 = *(const float4*)(p2t + (size_t)j0*C2c + c0);
        float4 v1 = *(const float4*)(p2t + (size_t)j1*C2c + c0);
        float4 v2 = *(const float4*)(p2t + (size_t)j2*C2c + c0);
        float r0 = fmaf(w2, v2.x, fmaf(w1, v1.x, w0*v0.x));
        float r1 = fmaf(w2, v2.y, fmaf(w1, v1.y, w0*v0.y));
        float r2 = fmaf(w2, v2.z, fmaf(w1, v1.z, w0*v0.z));
        float r3 = fmaf(w2, v2.w, fmaf(w1, v1.w, w0*v0.w));
        sc[c0+0][nl] = __float2half_rn(r0);
        sc[c0+1][nl] = __float2half_rn(r1);
        sc[c0+2][nl] = __float2half_rn(r2);
        sc[c0+3][nl] = __float2half_rn(r3);
    }
    __syncthreads();
    __half* xout = d_itph + (size_t)b*C2c*NN + n0;
    int nl2 = (t & 15) * 2;
    int cc0 = t >> 4;
    #pragma unroll
    for (int c = cc0; c < C2c; c += 16) {
        __half2 hv;
        hv.x = sc[c][nl2];
        hv.y = sc[c][nl2 + 1];
        *(__half2*)(xout + (size_t)c*NN + nl2) = hv;
    }
}

// ---------------- fp16 tensor-core GEMM (R16 verbatim) ----------------
template<int KTOT, bool L2MODE>
__global__ void __launch_bounds__(256) gemm_f16(
    const __half* __restrict__ AimgH,
    const float* __restrict__ Xp1,
    const __half* __restrict__ Xh,
    __half* __restrict__ Yh,
    const float* __restrict__ bias,
    const float* __restrict__ sumIn, const float* __restrict__ sqIn,
    const float* __restrict__ gamma, const float* __restrict__ beta,
    float* __restrict__ sumOut, float* __restrict__ sqOut)
{
    constexpr int NC = KTOT / 32;
    __shared__ __align__(16) uint4    As[2][1024];
    __shared__ __align__(16) uint32_t Bs[2][1024];
    __shared__ float redS[CO], redQ[CO];
    __shared__ float sA[CO], sB[CO];

    const uint32_t* Aimg = (const uint32_t*)AimgH;
    int t = threadIdx.x, l = t & 31, w = t >> 5;
    int wm = w >> 1, wn = w & 1;
    int g = l >> 2, tq = l & 3;
    int b = blockIdx.y, nT = blockIdx.x * 64;

    redS[t] = 0.f; redQ[t] = 0.f;
    if (L2MODE) {
        float m = sumIn[t] * (1.0f/COUNT_BN);
        float v = sqIn[t]  * (1.0f/COUNT_BN) - m*m;
        float inv = rsqrtf(v + 1e-5f);
        float a = gamma[t] * inv;
        sA[t] = a;
        sB[t] = beta[t] - a*m;
    }
    __syncthreads();

    int kp = t >> 4, n4 = t & 15;

    uint32_t Doff[4];
    #pragma unroll
    for (int bnl = 0; bnl < 4; bnl++)
        Doff[bnl] = (uint32_t)(tq*64 + wn*32 + ((bnl ^ tq) << 3) + g);

    float acc[4][4][4];
    #pragma unroll
    for (int i = 0; i < 4; i++)
        #pragma unroll
        for (int j = 0; j < 4; j++)
            #pragma unroll
            for (int r = 0; r < 4; r++) acc[i][j][r] = 0.f;

    float pv[8];
    auto stageB = [&](int c) {
        int k0 = c*32 + 2*kp;
        bool useH = L2MODE || (k0 >= C1c);
        if (useH) {
            int kk = L2MODE ? k0 : (k0 - C1c);
            const __half* bh = Xh + (size_t)b*C2c*NN + (size_t)kk*NN + nT + 4*n4;
            uint2 u0 = *(const uint2*)bh;
            uint2 u1 = *(const uint2*)(bh + NN);
            if (L2MODE) {
                __half2 h;
                h = *(__half2*)&u0.x; pv[0] = __low2float(h); pv[1] = __high2float(h);
                h = *(__half2*)&u0.y; pv[2] = __low2float(h); pv[3] = __high2float(h);
                h = *(__half2*)&u1.x; pv[4] = __low2float(h); pv[5] = __high2float(h);
                h = *(__half2*)&u1.y; pv[6] = __low2float(h); pv[7] = __high2float(h);
            } else {
                pv[0] = __uint_as_float(u0.x);
                pv[1] = __uint_as_float(u0.y);
                pv[2] = __uint_as_float(u1.x);
                pv[3] = __uint_as_float(u1.y);
            }
        } else {
            const float* base = Xp1 + (size_t)b*C1c*NN + (size_t)k0*NN + nT + 4*n4;
            float4 v0 = *(const float4*)base;
            float4 v1 = *(const float4*)(base + NN);
            pv[0] = v0.x; pv[1] = v0.y; pv[2] = v0.z; pv[3] = v0.w;
            pv[4] = v1.x; pv[5] = v1.y; pv[6] = v1.z; pv[7] = v1.w;
        }
    };
    auto storeB = [&](int c, int buf) {
        uint4 u;
        if (L2MODE) {
            float f[8];
            #pragma unroll
            for (int j = 0; j < 8; j++) f[j] = pv[j];
            int kg0 = c*32 + 2*kp;
            float a0 = sA[kg0],   b0 = sB[kg0];
            float a1 = sA[kg0+1], b1 = sB[kg0+1];
            #pragma unroll
            for (int j = 0; j < 4; j++) f[j]   = gelu_exact(fmaf(a0, f[j],   b0));
            #pragma unroll
            for (int j = 0; j < 4; j++) f[j+4] = gelu_exact(fmaf(a1, f[j+4], b1));
            __half2 h;
            h = __floats2half2_rn(f[0], f[4]); u.x = *(uint32_t*)&h;
            h = __floats2half2_rn(f[1], f[5]); u.y = *(uint32_t*)&h;
            h = __floats2half2_rn(f[2], f[6]); u.z = *(uint32_t*)&h;
            h = __floats2half2_rn(f[3], f[7]); u.w = *(uint32_t*)&h;
        } else if (c*32 + 2*kp >= C1c) {
            uint32_t a0 = __float_as_uint(pv[0]);
            uint32_t a1 = __float_as_uint(pv[1]);
            uint32_t b0 = __float_as_uint(pv[2]);
            uint32_t b1 = __float_as_uint(pv[3]);
            u.x = __byte_perm(a0, b0, 0x5410);
            u.y = __byte_perm(a0, b0, 0x7632);
            u.z = __byte_perm(a1, b1, 0x5410);
            u.w = __byte_perm(a1, b1, 0x7632);
        } else {
            __half2 h;
            h = __floats2half2_rn(pv[0], pv[4]); u.x = *(uint32_t*)&h;
            h = __floats2half2_rn(pv[1], pv[5]); u.y = *(uint32_t*)&h;
            h = __floats2half2_rn(pv[2], pv[6]); u.z = *(uint32_t*)&h;
            h = __floats2half2_rn(pv[3], pv[7]); u.w = *(uint32_t*)&h;
        }
        ((uint4*)Bs[buf])[kp*16 + (n4 ^ ((kp & 3) << 1))] = u;
    };
    auto stageA = [&](int c, int buf) {
        const uint32_t* src = Aimg + (size_t)c*4096 + t*4;
        uint32_t base = smem_u32(&As[buf][0]);
        #pragma unroll
        for (int j = 0; j < 4; j++)
            cp16(base + (uint32_t)(t + j*256)*16u, src + j*1024);
    };
    auto compute = [&](int buf) {
        const uint32_t* bs = Bs[buf];
        uint4 af[4][2];
        #pragma unroll
        for (int mf = 0; mf < 4; mf++)
            #pragma unroll
            for (int bk = 0; bk < 2; bk++)
                af[mf][bk] = As[buf][((wm*4 + mf)*2 + bk)*32 + l];
        uint32_t bf[4][2][2];
        #pragma unroll
        for (int bnl = 0; bnl < 4; bnl++) {
            #pragma unroll
            for (int bk = 0; bk < 2; bk++) {
                bf[bnl][bk][0] = bs[Doff[bnl] + bk*512];
                bf[bnl][bk][1] = bs[Doff[bnl] + bk*512 + 256];
            }
        }
        #pragma unroll
        for (int mf = 0; mf < 4; mf++)
            #pragma unroll
            for (int bnl = 0; bnl < 4; bnl++)
                #pragma unroll
                for (int bk = 0; bk < 2; bk++)
                    MMA_F16(acc[mf][bnl], af[mf][bk], bf[bnl][bk][0], bf[bnl][bk][1]);
    };

    stageB(0);
    stageA(0, 0); cp_commit();
    storeB(0, 0);
    #pragma unroll 2
    for (int c = 0; c < NC; c++) {
        int buf = c & 1;
        cp_wait0();
        __syncthreads();
        if (c + 1 < NC) { stageB(c + 1); stageA(c + 1, buf ^ 1); cp_commit(); }
        compute(buf);
        if (c + 1 < NC) storeB(c + 1, buf ^ 1);
    }

    // ---- epilogue: bias, fp16 store, stats ----
    #pragma unroll
    for (int mf = 0; mf < 4; mf++) {
        int o_lo = wm*64 + mf*16 + g;
        int o_hi = o_lo + 8;
        float bl = bias[b*CO + o_lo];
        float bh = bias[b*CO + o_hi];
        float sl = 0.f, ql = 0.f, sh = 0.f, qh = 0.f;
        #pragma unroll
        for (int bnl = 0; bnl < 4; bnl++) {
            int col = nT + wn*32 + bnl*8 + 2*tq;
            float v0 = acc[mf][bnl][0] + bl;
            float v1 = acc[mf][bnl][1] + bl;
            float v2 = acc[mf][bnl][2] + bh;
            float v3 = acc[mf][bnl][3] + bh;
            __half2 hlo = __floats2half2_rn(v0, v1);
            __half2 hhi = __floats2half2_rn(v2, v3);
            *(__half2*)(Yh + (size_t)b*CO*NN + (size_t)o_lo*NN + col) = hlo;
            *(__half2*)(Yh + (size_t)b*CO*NN + (size_t)o_hi*NN + col) = hhi;
            sl += v0 + v1; ql += v0*v0 + v1*v1;
            sh += v2 + v3; qh += v2*v2 + v3*v3;
        }
        #pragma unroll
        for (int off = 1; off <= 2; off <<= 1) {
            sl += __shfl_xor_sync(0xffffffffu, sl, off);
            ql += __shfl_xor_sync(0xffffffffu, ql, off);
            sh += __shfl_xor_sync(0xffffffffu, sh, off);
            qh += __shfl_xor_sync(0xffffffffu, qh, off);
        }
        if (tq == 0) {
            atomicAdd(&redS[o_lo], sl);
            atomicAdd(&redQ[o_lo], ql);
            atomicAdd(&redS[o_hi], sh);
            atomicAdd(&redQ[o_hi], qh);
        }
    }
    __syncthreads();
    atomicAdd(&sumOut[t], redS[t]);
    atomicAdd(&sqOut[t],  redQ[t]);
}

// ---------------- final: BN2 finalize + gelu in one pass, fp16 -> fp32 ----------------
__global__ void __launch_bounds__(256) final_kernel(
    const __half* __restrict__ y2h,
    const float* __restrict__ sum2, const float* __restrict__ sq2,
    const float* __restrict__ gamma, const float* __restrict__ beta,
    float* __restrict__ out)
{
    size_t i8 = (size_t)blockIdx.x * 256 + threadIdx.x;
    size_t total8 = (size_t)BB*CO*NN/8;
    if (i8 >= total8) return;
    uint4 u = ((const uint4*)y2h)[i8];
    size_t i = i8 * 8;
    int c = (int)((i >> 13) & 255);
    float m = sum2[c] * (1.0f/COUNT_BN);
    float v = sq2[c]  * (1.0f/COUNT_BN) - m*m;
    float inv = rsqrtf(v + 1e-5f);
    float a = gamma[c] * inv;
    float bo = beta[c] - a*m;
    const __half2* hp = (const __half2*)&u;
    float4 o0, o1;
    float2 f;
    f = __half22float2(hp[0]); o0.x = gelu_exact(fmaf(a, f.x, bo)); o0.y = gelu_exact(fmaf(a, f.y, bo));
    f = __half22float2(hp[1]); o0.z = gelu_exact(fmaf(a, f.x, bo)); o0.w = gelu_exact(fmaf(a, f.y, bo));
    f = __half22float2(hp[2]); o1.x = gelu_exact(fmaf(a, f.x, bo)); o1.y = gelu_exact(fmaf(a, f.y, bo));
    f = __half22float2(hp[3]); o1.z = gelu_exact(fmaf(a, f.x, bo)); o1.w = gelu_exact(fmaf(a, f.y, bo));
    ((float4*)out)[i8*2 + 0] = o0;
    ((float4*)out)[i8*2 + 1] = o1;
}

// ---------------- launch ----------------
extern "C" void kernel_launch(void* const* d_in, const int* in_sizes, int n_in,
                              void* d_out, int out_size)
{
    const float* xyz1    = (const float*)d_in[0];
    const float* xyz2    = (const float*)d_in[1];
    const float* points1 = (const float*)d_in[2];
    const float* points2 = (const float*)d_in[3];
    const float* t_embed = (const float*)d_in[4];
    const float* w_t1 = (const float*)d_in[5];
    const float* b_t1 = (const float*)d_in[6];
    const float* w_c1 = (const float*)d_in[7];
    const float* b_c1 = (const float*)d_in[8];
    const float* g1   = (const float*)d_in[9];
    const float* be1  = (const float*)d_in[10];
    const float* w_t2 = (const float*)d_in[11];
    const float* b_t2 = (const float*)d_in[12];
    const float* w_c2 = (const float*)d_in[13];
    const float* b_c2 = (const float*)d_in[14];
    const float* g2   = (const float*)d_in[15];
    const float* be2  = (const float*)d_in[16];
    float* out = (float*)d_out;

    float *p_bias1, *p_bias2;
    float *p_sum1, *p_sq1, *p_sum2, *p_sq2;
    __half *p_itph, *p_y1h, *p_y2h, *p_w1i, *p_w2i;
    cudaGetSymbolAddress((void**)&p_itph,  d_itph);
    cudaGetSymbolAddress((void**)&p_y1h,   d_y1h);
    cudaGetSymbolAddress((void**)&p_y2h,   d_y2h);
    cudaGetSymbolAddress((void**)&p_bias1, d_bias1);
    cudaGetSymbolAddress((void**)&p_bias2, d_bias2);
    cudaGetSymbolAddress((void**)&p_sum1,  d_sum1);
    cudaGetSymbolAddress((void**)&p_sq1,   d_sq1);
    cudaGetSymbolAddress((void**)&p_sum2,  d_sum2);
    cudaGetSymbolAddress((void**)&p_sq2,   d_sq2);
    cudaGetSymbolAddress((void**)&p_w1i,   d_w1img);
    cudaGetSymbolAddress((void**)&p_w2i,   d_w2img);

    // 1. mega-prep: top3(4-way) + transpose + weight perms + biases + stat zero
    mega_prep<<<MB_TOTAL, 256>>>(xyz1, xyz2, points2, t_embed,
                                 w_t1, b_t1, w_c1, b_c1,
                                 w_t2, b_t2, w_c2, b_c2);

    // 2. interpolation (float4 gather)
    interp_kernel<<<dim3(NN/32, BB), 256>>>();

    // 3. Layer 1: y1h = fp16(w_c1 @ [points1; itph] + bias1), stats -> sum1/sq1
    gemm_f16<CIN, false><<<dim3(NN/64, BB), 256>>>(
        p_w1i, points1, p_itph, p_y1h, p_bias1,
        nullptr, nullptr, nullptr, nullptr, p_sum1, p_sq1);

    // 4. Layer 2: y2h = fp16(w_c2 @ gelu(bn1(y1h)) + bias2); BN1 finalized in-kernel
    gemm_f16<CO, true><<<dim3(NN/64, BB), 256>>>(
        p_w2i, (const float*)nullptr, p_y1h, p_y2h, p_bias2,
        p_sum1, p_sq1, g1, be1, p_sum2, p_sq2);

    // 5. final: BN2 finalize + gelu -> fp32 out
    final_kernel<<<(unsigned)(((size_t)BB*CO*NN/8 + 255)/256), 256>>>(
        p_y2h, p_sum2, p_sq2, g2, be2, out);
}